// round 2
// baseline (speedup 1.0000x reference)
#include <cuda_runtime.h>
#include <math.h>

// Problem constants
#define BATCH 16
#define CDIM  512
#define NDIM  4096   // 64*64

// Scratch: energy / attention matrix, 16 * 512 * 512 floats = 16 MB
__device__ float g_energy[BATCH * CDIM * CDIM];

// ---------------------------------------------------------------------------
// Kernel 1: energy[b,i,j] = sum_n x_low[b,i,n] * x_high[b,j,n]   (NT SGEMM)
// grid: (4, 4, 16)  block: 256 threads, 128x128 tile, BK=8, 8x8 per thread
// ---------------------------------------------------------------------------
__global__ __launch_bounds__(256)
void energy_kernel(const float* __restrict__ x_low,
                   const float* __restrict__ x_high)
{
    const int b = blockIdx.z;
    const float* Q = x_low  + (size_t)b * CDIM * NDIM;
    const float* K = x_high + (size_t)b * CDIM * NDIM;
    float* E = g_energy + (size_t)b * CDIM * CDIM;

    __shared__ float As[8][128];   // [k][i]
    __shared__ float Bs[8][128];   // [k][j]

    const int tid = threadIdx.x;
    const int threadCol = tid & 15;   // j sub-tile (0..15)
    const int threadRow = tid >> 4;   // i sub-tile (0..15)

    const int loadRow = tid >> 1;          // 0..127
    const int loadCol = (tid & 1) * 4;     // 0 or 4

    const size_t aBase = (size_t)(blockIdx.y * 128 + loadRow) * NDIM + loadCol;
    const size_t bBase = (size_t)(blockIdx.x * 128 + loadRow) * NDIM + loadCol;

    float acc[8][8];
    #pragma unroll
    for (int m = 0; m < 8; m++)
        #pragma unroll
        for (int n = 0; n < 8; n++) acc[m][n] = 0.f;

    for (int k0 = 0; k0 < NDIM; k0 += 8) {
        float4 a4 = *reinterpret_cast<const float4*>(Q + aBase + k0);
        float4 b4 = *reinterpret_cast<const float4*>(K + bBase + k0);

        As[loadCol + 0][loadRow] = a4.x;
        As[loadCol + 1][loadRow] = a4.y;
        As[loadCol + 2][loadRow] = a4.z;
        As[loadCol + 3][loadRow] = a4.w;
        Bs[loadCol + 0][loadRow] = b4.x;
        Bs[loadCol + 1][loadRow] = b4.y;
        Bs[loadCol + 2][loadRow] = b4.z;
        Bs[loadCol + 3][loadRow] = b4.w;
        __syncthreads();

        #pragma unroll
        for (int k = 0; k < 8; k++) {
            float4 m0 = *reinterpret_cast<const float4*>(&As[k][threadRow * 8]);
            float4 m1 = *reinterpret_cast<const float4*>(&As[k][threadRow * 8 + 4]);
            float4 n0 = *reinterpret_cast<const float4*>(&Bs[k][threadCol * 8]);
            float4 n1 = *reinterpret_cast<const float4*>(&Bs[k][threadCol * 8 + 4]);
            float rm[8] = {m0.x, m0.y, m0.z, m0.w, m1.x, m1.y, m1.z, m1.w};
            float rn[8] = {n0.x, n0.y, n0.z, n0.w, n1.x, n1.y, n1.z, n1.w};
            #pragma unroll
            for (int m = 0; m < 8; m++)
                #pragma unroll
                for (int n = 0; n < 8; n++)
                    acc[m][n] = fmaf(rm[m], rn[n], acc[m][n]);
        }
        __syncthreads();
    }

    // Write 128x128 tile of energy
    const int iBase = blockIdx.y * 128 + threadRow * 8;
    const int jBase = blockIdx.x * 128 + threadCol * 8;
    #pragma unroll
    for (int m = 0; m < 8; m++) {
        float4 v0 = make_float4(acc[m][0], acc[m][1], acc[m][2], acc[m][3]);
        float4 v1 = make_float4(acc[m][4], acc[m][5], acc[m][6], acc[m][7]);
        float* dst = E + (size_t)(iBase + m) * CDIM + jBase;
        *reinterpret_cast<float4*>(dst)     = v0;
        *reinterpret_cast<float4*>(dst + 4) = v1;
    }
}

// ---------------------------------------------------------------------------
// Kernel 2: inverted softmax per row, in place.
// attention[j] = exp(rowmin - e[j]) / sum_j exp(rowmin - e[j])
// (identical to softmax(rowmax - e) of the reference)
// grid: 16*512 blocks of 256 threads (2 elements/thread)
// ---------------------------------------------------------------------------
__global__ __launch_bounds__(256)
void softmax_kernel()
{
    float* row = g_energy + (size_t)blockIdx.x * CDIM;
    const int tid = threadIdx.x;

    float v0 = row[tid];
    float v1 = row[tid + 256];

    __shared__ float red[256];
    red[tid] = fminf(v0, v1);
    __syncthreads();
    #pragma unroll
    for (int s = 128; s > 0; s >>= 1) {
        if (tid < s) red[tid] = fminf(red[tid], red[tid + s]);
        __syncthreads();
    }
    const float rowmin = red[0];
    __syncthreads();

    float e0 = expf(rowmin - v0);
    float e1 = expf(rowmin - v1);

    red[tid] = e0 + e1;
    __syncthreads();
    #pragma unroll
    for (int s = 128; s > 0; s >>= 1) {
        if (tid < s) red[tid] += red[tid + s];
        __syncthreads();
    }
    const float inv = 1.0f / red[0];

    row[tid]       = e0 * inv;
    row[tid + 256] = e1 * inv;
}

// ---------------------------------------------------------------------------
// Kernel 3: out[b,i,n] = gamma * sum_j att[b,i,j]*x_high[b,j,n] + x_low[b,i,n]
// NN SGEMM, grid: (32, 4, 16), 128x128 tile, BK=8, 8x8 per thread
// ---------------------------------------------------------------------------
__global__ __launch_bounds__(256)
void out_kernel(const float* __restrict__ x_high,
                const float* __restrict__ x_low,
                const float* __restrict__ gamma,
                float* __restrict__ out)
{
    const int b = blockIdx.z;
    const float* A = g_energy + (size_t)b * CDIM * CDIM;          // attention
    const float* Bm = x_high + (size_t)b * CDIM * NDIM;

    __shared__ float As[8][128];   // [k][i] (transposed store)
    __shared__ float Bs[8][128];   // [k][n] (natural store)

    const int tid = threadIdx.x;
    const int threadCol = tid & 15;
    const int threadRow = tid >> 4;

    // A-tile loader: row i = y*128 + tid/2, cols k0 + (tid&1)*4
    const int aRow = tid >> 1;
    const int aCol = (tid & 1) * 4;
    const size_t aBase = (size_t)(blockIdx.y * 128 + aRow) * CDIM + aCol;

    // B-tile loader: row k0 + tid/32, cols x*128 + (tid%32)*4
    const int bRow = tid >> 5;             // 0..7
    const int bCol = (tid & 31) * 4;       // 0..124
    const size_t bBase = (size_t)bRow * NDIM + blockIdx.x * 128 + bCol;

    float acc[8][8];
    #pragma unroll
    for (int m = 0; m < 8; m++)
        #pragma unroll
        for (int n = 0; n < 8; n++) acc[m][n] = 0.f;

    for (int k0 = 0; k0 < CDIM; k0 += 8) {
        float4 a4 = *reinterpret_cast<const float4*>(A + aBase + k0);
        float4 b4 = *reinterpret_cast<const float4*>(Bm + bBase + (size_t)k0 * NDIM);

        As[aCol + 0][aRow] = a4.x;
        As[aCol + 1][aRow] = a4.y;
        As[aCol + 2][aRow] = a4.z;
        As[aCol + 3][aRow] = a4.w;
        *reinterpret_cast<float4*>(&Bs[bRow][bCol]) = b4;
        __syncthreads();

        #pragma unroll
        for (int k = 0; k < 8; k++) {
            float4 m0 = *reinterpret_cast<const float4*>(&As[k][threadRow * 8]);
            float4 m1 = *reinterpret_cast<const float4*>(&As[k][threadRow * 8 + 4]);
            float4 n0 = *reinterpret_cast<const float4*>(&Bs[k][threadCol * 8]);
            float4 n1 = *reinterpret_cast<const float4*>(&Bs[k][threadCol * 8 + 4]);
            float rm[8] = {m0.x, m0.y, m0.z, m0.w, m1.x, m1.y, m1.z, m1.w};
            float rn[8] = {n0.x, n0.y, n0.z, n0.w, n1.x, n1.y, n1.z, n1.w};
            #pragma unroll
            for (int m = 0; m < 8; m++)
                #pragma unroll
                for (int n = 0; n < 8; n++)
                    acc[m][n] = fmaf(rm[m], rn[n], acc[m][n]);
        }
        __syncthreads();
    }

    const float g = __ldg(gamma);
    const int iBase = blockIdx.y * 128 + threadRow * 8;
    const int nBase = blockIdx.x * 128 + threadCol * 8;
    #pragma unroll
    for (int m = 0; m < 8; m++) {
        const size_t idx = ((size_t)b * CDIM + (iBase + m)) * NDIM + nBase;
        float4 x0 = *reinterpret_cast<const float4*>(x_low + idx);
        float4 x1 = *reinterpret_cast<const float4*>(x_low + idx + 4);
        float4 r0, r1;
        r0.x = fmaf(g, acc[m][0], x0.x);
        r0.y = fmaf(g, acc[m][1], x0.y);
        r0.z = fmaf(g, acc[m][2], x0.z);
        r0.w = fmaf(g, acc[m][3], x0.w);
        r1.x = fmaf(g, acc[m][4], x1.x);
        r1.y = fmaf(g, acc[m][5], x1.y);
        r1.z = fmaf(g, acc[m][6], x1.z);
        r1.w = fmaf(g, acc[m][7], x1.w);
        *reinterpret_cast<float4*>(out + idx)     = r0;
        *reinterpret_cast<float4*>(out + idx + 4) = r1;
    }
}

// ---------------------------------------------------------------------------
extern "C" void kernel_launch(void* const* d_in, const int* in_sizes, int n_in,
                              void* d_out, int out_size)
{
    const float* x_high = (const float*)d_in[0];
    const float* x_low  = (const float*)d_in[1];
    const float* gamma  = (const float*)d_in[2];
    float* out = (float*)d_out;

    dim3 g1(CDIM / 128, CDIM / 128, BATCH);          // (4, 4, 16)
    energy_kernel<<<g1, 256>>>(x_low, x_high);

    softmax_kernel<<<BATCH * CDIM, 256>>>();         // 8192 rows

    dim3 g2(NDIM / 128, CDIM / 128, BATCH);          // (32, 4, 16)
    out_kernel<<<g2, 256>>>(x_high, x_low, gamma, out);
}

// round 4
// speedup vs baseline: 1.9696x; 1.9696x over previous
#include <cuda_runtime.h>
#include <cuda_bf16.h>
#include <cstdint>
#include <math.h>

#define BATCH 16
#define CDIM  512
#define NDIM  4096

// ---------------------------------------------------------------------------
// Device scratch
// ---------------------------------------------------------------------------
__device__ float g_energy[BATCH * CDIM * CDIM];                 // fp32 energy
__device__ __nv_bfloat16 g_xh_hi[BATCH * CDIM * NDIM];          // x_high [b,j,n]
__device__ __nv_bfloat16 g_xh_lo[BATCH * CDIM * NDIM];
__device__ __nv_bfloat16 g_xl_hi[BATCH * CDIM * NDIM];          // x_low  [b,i,n]
__device__ __nv_bfloat16 g_xl_lo[BATCH * CDIM * NDIM];
__device__ __nv_bfloat16 g_xhT_hi[BATCH * NDIM * CDIM];         // x_high^T [b,n,j]
__device__ __nv_bfloat16 g_xhT_lo[BATCH * NDIM * CDIM];
__device__ __nv_bfloat16 g_att_hi[BATCH * CDIM * CDIM];         // attention [b,i,j]
__device__ __nv_bfloat16 g_att_lo[BATCH * CDIM * CDIM];

// ---------------------------------------------------------------------------
// PTX helpers (sm_100-safe: mma.sync / ldmatrix / cp.async only)
// ---------------------------------------------------------------------------
__device__ __forceinline__ uint32_t smem_u32(const void* p) {
    uint32_t a;
    asm("{ .reg .u64 t; cvta.to.shared.u64 t, %1; cvt.u32.u64 %0, t; }"
        : "=r"(a) : "l"(p));
    return a;
}

#define CP_ASYNC16(dst, src) \
    asm volatile("cp.async.cg.shared.global [%0], [%1], 16;" :: "r"(dst), "l"(src))
#define CP_COMMIT() asm volatile("cp.async.commit_group;" ::: "memory")
#define CP_WAIT1()  asm volatile("cp.async.wait_group 1;" ::: "memory")
#define CP_WAIT0()  asm volatile("cp.async.wait_group 0;" ::: "memory")

#define LDSM_X4(r0, r1, r2, r3, addr) \
    asm volatile("ldmatrix.sync.aligned.m8n8.x4.shared.b16 {%0,%1,%2,%3}, [%4];" \
        : "=r"(r0), "=r"(r1), "=r"(r2), "=r"(r3) : "r"(addr))

#define MMA_BF16(c, a0, a1, a2, a3, b0, b1) \
    asm volatile("mma.sync.aligned.m16n8k16.row.col.f32.bf16.bf16.f32 " \
        "{%0,%1,%2,%3}, {%4,%5,%6,%7}, {%8,%9}, {%0,%1,%2,%3};" \
        : "+f"((c)[0]), "+f"((c)[1]), "+f"((c)[2]), "+f"((c)[3]) \
        : "r"(a0), "r"(a1), "r"(a2), "r"(a3), "r"(b0), "r"(b1))

// ---------------------------------------------------------------------------
// Kernel: split fp32 -> bf16 hi + lo.  WHICH: 0 = x_high, 1 = x_low
// ---------------------------------------------------------------------------
template<int WHICH>
__global__ __launch_bounds__(256)
void split_kernel(const float* __restrict__ src)
{
    __nv_bfloat16* hi = (WHICH == 0) ? g_xh_hi : g_xl_hi;
    __nv_bfloat16* lo = (WHICH == 0) ? g_xh_lo : g_xl_lo;
    const int i = blockIdx.x * 256 + threadIdx.x;        // one float4 per thread
    float4 v = reinterpret_cast<const float4*>(src)[i];
    __nv_bfloat16 h0 = __float2bfloat16_rn(v.x);
    __nv_bfloat16 h1 = __float2bfloat16_rn(v.y);
    __nv_bfloat16 h2 = __float2bfloat16_rn(v.z);
    __nv_bfloat16 h3 = __float2bfloat16_rn(v.w);
    __nv_bfloat16 l0 = __float2bfloat16_rn(v.x - __bfloat162float(h0));
    __nv_bfloat16 l1 = __float2bfloat16_rn(v.y - __bfloat162float(h1));
    __nv_bfloat16 l2 = __float2bfloat16_rn(v.z - __bfloat162float(h2));
    __nv_bfloat16 l3 = __float2bfloat16_rn(v.w - __bfloat162float(h3));
    __nv_bfloat162* hp = reinterpret_cast<__nv_bfloat162*>(hi);
    __nv_bfloat162* lp = reinterpret_cast<__nv_bfloat162*>(lo);
    hp[2 * i]     = __nv_bfloat162(h0, h1);
    hp[2 * i + 1] = __nv_bfloat162(h2, h3);
    lp[2 * i]     = __nv_bfloat162(l0, l1);
    lp[2 * i + 1] = __nv_bfloat162(l2, l3);
}

// ---------------------------------------------------------------------------
// Kernel: transpose x_high -> xhT (bf16 hi/lo), [b,j,n] -> [b,n,j]
// ---------------------------------------------------------------------------
__global__ __launch_bounds__(256)
void transpose_kernel(const float* __restrict__ xh)
{
    __shared__ __nv_bfloat16 sh[32][33];
    __shared__ __nv_bfloat16 sl[32][33];
    const int b = blockIdx.z;
    const int n0 = blockIdx.x * 32;
    const int j0 = blockIdx.y * 32;
    const int tx = threadIdx.x, ty = threadIdx.y;

    #pragma unroll
    for (int k = 0; k < 4; k++) {
        int j = j0 + ty + 8 * k;
        float v = xh[((size_t)b * CDIM + j) * NDIM + n0 + tx];
        __nv_bfloat16 h = __float2bfloat16_rn(v);
        sh[ty + 8 * k][tx] = h;
        sl[ty + 8 * k][tx] = __float2bfloat16_rn(v - __bfloat162float(h));
    }
    __syncthreads();
    #pragma unroll
    for (int k = 0; k < 4; k++) {
        int n = n0 + ty + 8 * k;
        size_t o = ((size_t)b * NDIM + n) * CDIM + j0 + tx;
        g_xhT_hi[o] = sh[tx][ty + 8 * k];
        g_xhT_lo[o] = sl[tx][ty + 8 * k];
    }
}

// ---------------------------------------------------------------------------
// Kernel: inverted softmax per row (fp32 energy -> bf16 hi/lo attention)
// ---------------------------------------------------------------------------
__global__ __launch_bounds__(256)
void softmax_kernel()
{
    const size_t rbase = (size_t)blockIdx.x * CDIM;
    const float* row = g_energy + rbase;
    const int tid = threadIdx.x;

    float v0 = row[tid];
    float v1 = row[tid + 256];

    __shared__ float red[256];
    red[tid] = fminf(v0, v1);
    __syncthreads();
    #pragma unroll
    for (int s = 128; s > 0; s >>= 1) {
        if (tid < s) red[tid] = fminf(red[tid], red[tid + s]);
        __syncthreads();
    }
    const float rowmin = red[0];
    __syncthreads();

    float e0 = expf(rowmin - v0);
    float e1 = expf(rowmin - v1);
    red[tid] = e0 + e1;
    __syncthreads();
    #pragma unroll
    for (int s = 128; s > 0; s >>= 1) {
        if (tid < s) red[tid] += red[tid + s];
        __syncthreads();
    }
    const float inv = 1.0f / red[0];
    float a0 = e0 * inv, a1 = e1 * inv;

    __nv_bfloat16 h0 = __float2bfloat16_rn(a0);
    __nv_bfloat16 h1 = __float2bfloat16_rn(a1);
    g_att_hi[rbase + tid]       = h0;
    g_att_hi[rbase + tid + 256] = h1;
    g_att_lo[rbase + tid]       = __float2bfloat16_rn(a0 - __bfloat162float(h0));
    g_att_lo[rbase + tid + 256] = __float2bfloat16_rn(a1 - __bfloat162float(h1));
}

// ---------------------------------------------------------------------------
// Split-bf16 warp-MMA GEMM (NT, K-contiguous operands).
//   D = Ahi*Bhi + Ahi*Blo + Alo*Bhi  (fp32 accum)
// MODE 0 (energy): A = x_low  [b,512,K=4096], B = x_high [b,512,K=4096] -> g_energy
// MODE 1 (out):    A = att    [b,512,K=512],  B = xhT    [b,4096,K=512]
//                  -> out = gamma*D + x_low
// Block 128x128, BK=32, 8 warps of 64x32, cp.async double buffer.
// ---------------------------------------------------------------------------
#define BK 32
#define RS 80           // smem row pitch in bytes (32 bf16 + 8 pad)
#define TILE_B (128 * RS)          // 10240 B per operand tile
#define STAGE_B (4 * TILE_B)       // Ahi, Alo, Bhi, Blo

template<int MODE>
__global__ __launch_bounds__(256, 1)
void mma_gemm(const float* __restrict__ x_low, const float* __restrict__ gamma,
              float* __restrict__ out)
{
    constexpr int KTOT = (MODE == 0) ? NDIM : CDIM;
    constexpr int NTOT = (MODE == 0) ? CDIM : NDIM;
    constexpr int NCH  = KTOT / BK;

    extern __shared__ char smem[];
    const uint32_t sbase = smem_u32(smem);
    const int tid = threadIdx.x;
    const int wid = tid >> 5, lane = tid & 31;
    const int b = blockIdx.z;
    const int mBase = blockIdx.y * 128;
    const int nBase = blockIdx.x * 128;

    const __nv_bfloat16* Ahi = (MODE == 0) ? g_xl_hi : g_att_hi;
    const __nv_bfloat16* Alo = (MODE == 0) ? g_xl_lo : g_att_lo;
    const __nv_bfloat16* Bhi = (MODE == 0) ? g_xh_hi : g_xhT_hi;
    const __nv_bfloat16* Blo = (MODE == 0) ? g_xh_lo : g_xhT_lo;

    const __nv_bfloat16* srcs[4] = {
        Ahi + ((size_t)b * CDIM + mBase) * KTOT,
        Alo + ((size_t)b * CDIM + mBase) * KTOT,
        Bhi + ((size_t)b * NTOT + nBase) * KTOT,
        Blo + ((size_t)b * NTOT + nBase) * KTOT
    };

    // loader indices: 512 x 16B per tile; thread does 2 chunks per tile
    const int ldRow0 = tid >> 2;            // 0..63
    const int ldC0   = tid & 3;

    auto load_stage = [&](int stage, int k0) {
        const uint32_t sb = sbase + stage * STAGE_B;
        #pragma unroll
        for (int tIdx = 0; tIdx < 4; tIdx++) {
            const __nv_bfloat16* src = srcs[tIdx];
            const uint32_t tb = sb + tIdx * TILE_B;
            #pragma unroll
            for (int t = 0; t < 2; t++) {
                int row = ldRow0 + t * 64;
                CP_ASYNC16(tb + row * RS + ldC0 * 16,
                           src + (size_t)row * KTOT + k0 + ldC0 * 8);
            }
        }
    };

    // warp tile: wm in {0,1} (64 rows), wn in {0..3} (32 cols)
    const int wm = wid & 1, wn = wid >> 1;

    float acc[4][4][4];
    #pragma unroll
    for (int i = 0; i < 4; i++)
        #pragma unroll
        for (int j = 0; j < 4; j++)
            #pragma unroll
            for (int r = 0; r < 4; r++) acc[i][j][r] = 0.f;

    // ldmatrix lane addressing
    const int aRow = lane & 15;             // row within 16-row tile
    const int aCol8 = (lane >> 4) * 8;      // k sub-chunk 0/8
    const int bRow = (lane & 7) + ((lane >> 4) & 1) * 8;  // n within 16
    const int bCol8 = ((lane >> 3) & 1) * 8;              // k sub-chunk 0/8

    load_stage(0, 0);
    CP_COMMIT();

    for (int k = 0; k < NCH; k++) {
        if (k + 1 < NCH) {
            load_stage((k + 1) & 1, (k + 1) * BK);
            CP_COMMIT();
            CP_WAIT1();
        } else {
            CP_WAIT0();
        }
        __syncthreads();

        const uint32_t sb = sbase + (k & 1) * STAGE_B;
        #pragma unroll
        for (int p = 0; p < 3; p++) {
            const uint32_t Ab = sb + ((p == 2) ? TILE_B : 0);
            const uint32_t Bb = sb + ((p == 1) ? 3 * TILE_B : 2 * TILE_B);
            #pragma unroll
            for (int ks = 0; ks < 2; ks++) {
                const int kOff = ks * 16;
                uint32_t a[4][4];
                #pragma unroll
                for (int mt = 0; mt < 4; mt++) {
                    uint32_t addr = Ab + (wm * 64 + mt * 16 + aRow) * RS
                                  + (kOff + aCol8) * 2;
                    LDSM_X4(a[mt][0], a[mt][1], a[mt][2], a[mt][3], addr);
                }
                uint32_t bb[4][2];
                #pragma unroll
                for (int nt2 = 0; nt2 < 2; nt2++) {
                    uint32_t addr = Bb + (wn * 32 + nt2 * 16 + bRow) * RS
                                  + (kOff + bCol8) * 2;
                    uint32_t r0, r1, r2, r3;
                    LDSM_X4(r0, r1, r2, r3, addr);
                    bb[nt2 * 2 + 0][0] = r0; bb[nt2 * 2 + 0][1] = r1;
                    bb[nt2 * 2 + 1][0] = r2; bb[nt2 * 2 + 1][1] = r3;
                }
                #pragma unroll
                for (int mt = 0; mt < 4; mt++)
                    #pragma unroll
                    for (int nt = 0; nt < 4; nt++)
                        MMA_BF16(acc[mt][nt], a[mt][0], a[mt][1], a[mt][2], a[mt][3],
                                 bb[nt][0], bb[nt][1]);
            }
        }
        __syncthreads();
    }

    // Epilogue: acc frag c0,c1 -> (row l/4, col (l%4)*2), c2,c3 -> row+8
    const int fr = lane >> 2;
    const int fc = (lane & 3) * 2;
    if (MODE == 0) {
        float* E = g_energy + (size_t)b * CDIM * CDIM;
        #pragma unroll
        for (int mt = 0; mt < 4; mt++) {
            #pragma unroll
            for (int nt = 0; nt < 4; nt++) {
                int r0 = mBase + wm * 64 + mt * 16 + fr;
                int c  = nBase + wn * 32 + nt * 8 + fc;
                *reinterpret_cast<float2*>(E + (size_t)r0 * CDIM + c) =
                    make_float2(acc[mt][nt][0], acc[mt][nt][1]);
                *reinterpret_cast<float2*>(E + (size_t)(r0 + 8) * CDIM + c) =
                    make_float2(acc[mt][nt][2], acc[mt][nt][3]);
            }
        }
    } else {
        const float g = __ldg(gamma);
        #pragma unroll
        for (int mt = 0; mt < 4; mt++) {
            #pragma unroll
            for (int nt = 0; nt < 4; nt++) {
                int r0 = mBase + wm * 64 + mt * 16 + fr;
                int c  = nBase + wn * 32 + nt * 8 + fc;
                size_t o0 = ((size_t)b * CDIM + r0) * NDIM + c;
                size_t o1 = ((size_t)b * CDIM + r0 + 8) * NDIM + c;
                float2 x0 = *reinterpret_cast<const float2*>(x_low + o0);
                float2 x1 = *reinterpret_cast<const float2*>(x_low + o1);
                *reinterpret_cast<float2*>(out + o0) =
                    make_float2(fmaf(g, acc[mt][nt][0], x0.x),
                                fmaf(g, acc[mt][nt][1], x0.y));
                *reinterpret_cast<float2*>(out + o1) =
                    make_float2(fmaf(g, acc[mt][nt][2], x1.x),
                                fmaf(g, acc[mt][nt][3], x1.y));
            }
        }
    }
}

// ---------------------------------------------------------------------------
extern "C" void kernel_launch(void* const* d_in, const int* in_sizes, int n_in,
                              void* d_out, int out_size)
{
    const float* x_high = (const float*)d_in[0];
    const float* x_low  = (const float*)d_in[1];
    const float* gamma  = (const float*)d_in[2];
    float* out = (float*)d_out;

    const int SMEM = 2 * STAGE_B;   // 81920 B
    cudaFuncSetAttribute(mma_gemm<0>, cudaFuncAttributeMaxDynamicSharedMemorySize, SMEM);
    cudaFuncSetAttribute(mma_gemm<1>, cudaFuncAttributeMaxDynamicSharedMemorySize, SMEM);

    const int n4 = BATCH * CDIM * NDIM / 4;
    split_kernel<0><<<n4 / 256, 256>>>(x_high);
    split_kernel<1><<<n4 / 256, 256>>>(x_low);
    transpose_kernel<<<dim3(NDIM / 32, CDIM / 32, BATCH), dim3(32, 8)>>>(x_high);

    mma_gemm<0><<<dim3(CDIM / 128, CDIM / 128, BATCH), 256, SMEM>>>(nullptr, nullptr, nullptr);

    softmax_kernel<<<BATCH * CDIM, 256>>>();

    mma_gemm<1><<<dim3(NDIM / 128, CDIM / 128, BATCH), 256, SMEM>>>(x_low, gamma, out);
}